// round 14
// baseline (speedup 1.0000x reference)
#include <cuda_runtime.h>
#include <math.h>

#define HH 128
#define WW 128
#define NN 16384          // H*W
#define BB 2
#define DD 32
#define QQ 128
#define MM 16
#define EPSF 1e-8f

// ---------------- scratch (static device allocations; no cudaMalloc) --------
__device__ float g_feat1[BB*NN*DD];
__device__ float g_k   [BB*NN*DD];   // pre-normalized k-hat
__device__ float g_q   [BB*NN*DD];   // pre-normalized q-hat
__device__ float g_w   [BB*NN*25];   // unnormalized exp(cos) weights
__device__ float g_hA  [BB*NN*QQ];
__device__ float g_hB  [BB*NN*QQ];

// ---------------- conv1: (B,H,W,3) -> relu -> (B,H,W,32) --------------------
__global__ __launch_bounds__(512) void conv1_k(const float* __restrict__ x,
                        const float* __restrict__ w,
                        const float* __restrict__ bias) {
    __shared__ float sw[3*3*3*32];
    __shared__ float sb[32];
    for (int t = threadIdx.x; t < 864; t += 512) sw[t] = w[t];
    if (threadIdx.x < 32) sb[threadIdx.x] = bias[threadIdx.x];
    __syncthreads();

    int warp = threadIdx.x >> 5;
    int co   = threadIdx.x & 31;

    #pragma unroll
    for (int ii = 0; ii < 4; ii++) {
        int gid = blockIdx.x * 64 + ii*16 + warp;    // pixel in [0, B*N)
        int b = gid >> 14, p = gid & (NN-1);
        int i = p >> 7, j = p & 127;

        float acc = sb[co];
        #pragma unroll
        for (int ky = 0; ky < 3; ky++) {
            int yi = i + ky - 1;
            if ((unsigned)yi >= HH) continue;
            #pragma unroll
            for (int kx = 0; kx < 3; kx++) {
                int xj = j + kx - 1;
                if ((unsigned)xj >= WW) continue;
                const float* xp = x + ((size_t)((b << 14) | (yi << 7) | xj)) * 3;
                const float* wp = sw + (ky*3 + kx) * 3 * 32;
                #pragma unroll
                for (int ci = 0; ci < 3; ci++) acc += xp[ci] * wp[ci*32 + co];
            }
        }
        g_feat1[(size_t)gid*32 + co] = fmaxf(acc, 0.f);
    }
}

// ------- conv2 + fused k/q projection + normalization (k-hat, q-hat) --------
__global__ __launch_bounds__(512) void conv2kq_k(const float* __restrict__ w,
                          const float* __restrict__ bias,
                          const float* __restrict__ wk,
                          const float* __restrict__ bk,
                          const float* __restrict__ wq) {
    __shared__ float sw[3*3*32*32];
    __shared__ float swk[1024], swq[1024];
    __shared__ float sb[32], sbk[32];
    for (int t = threadIdx.x; t < 9216; t += 512) sw[t] = w[t];
    for (int t = threadIdx.x; t < 1024; t += 512) { swk[t] = wk[t]; swq[t] = wq[t]; }
    if (threadIdx.x < 32) { sb[threadIdx.x] = bias[threadIdx.x]; sbk[threadIdx.x] = bk[threadIdx.x]; }
    __syncthreads();

    int warp = threadIdx.x >> 5;
    int co   = threadIdx.x & 31;

    #pragma unroll 1
    for (int ii = 0; ii < 4; ii++) {
        int gid = blockIdx.x * 64 + ii*16 + warp;
        int b = gid >> 14, p = gid & (NN-1);
        int i = p >> 7, j = p & 127;

        float acc = sb[co];
        #pragma unroll
        for (int ky = 0; ky < 3; ky++) {
            int yi = i + ky - 1;
            if ((unsigned)yi >= HH) continue;
            #pragma unroll
            for (int kx = 0; kx < 3; kx++) {
                int xj = j + kx - 1;
                if ((unsigned)xj >= WW) continue;
                const float* fin = g_feat1 + ((size_t)((b << 14) | (yi << 7) | xj)) * 32;
                const float* wp  = sw + (ky*3 + kx) * 32 * 32;
                #pragma unroll
                for (int ci = 0; ci < 32; ci++) acc += fin[ci] * wp[ci*32 + co];
            }
        }
        float fv = fmaxf(acc, 0.f);

        float ka = sbk[co], qa = 0.f;
        #pragma unroll
        for (int ci = 0; ci < 32; ci++) {
            float f = __shfl_sync(0xffffffffu, fv, ci);
            ka += f * swk[ci*32 + co];
            qa += f * swq[ci*32 + co];
        }
        float ks = ka*ka, qs = qa*qa;
        #pragma unroll
        for (int o = 16; o; o >>= 1) {
            ks += __shfl_xor_sync(0xffffffffu, ks, o);
            qs += __shfl_xor_sync(0xffffffffu, qs, o);
        }
        float kinv = rsqrtf(fmaxf(ks, 1e-30f));
        float qinv = rsqrtf(fmaxf(qs, 1e-30f));
        g_k[(size_t)gid*32 + co] = ka * kinv;
        g_q[(size_t)gid*32 + co] = qa * qinv;
    }
}

// ---------------- edge weights: exp(dot(q-hat, k-hat)), tile-based ----------
__global__ void edgew_k() {
    __shared__ float sk[32*145];
    __shared__ float sq[64*32];

    int b = blockIdx.z;
    int ti0 = blockIdx.y << 3, tj0 = blockIdx.x << 3;
    int tid = threadIdx.x;
    size_t bbase = (size_t)b << 14;

    for (int t = tid; t < 1152; t += 256) {
        int hp = t >> 3, c4 = t & 7;
        int hr = hp / 12, hc = hp - hr*12;
        int gi = min(max(ti0 + hr - 2, 0), HH-1);
        int gj = min(max(tj0 + hc - 2, 0), WW-1);
        float4 v = ((const float4*)(g_k + (bbase + (gi << 7) + gj) * 32))[c4];
        sk[(c4*4+0)*145 + hp] = v.x;
        sk[(c4*4+1)*145 + hp] = v.y;
        sk[(c4*4+2)*145 + hp] = v.z;
        sk[(c4*4+3)*145 + hp] = v.w;
    }
    for (int t = tid; t < 512; t += 256) {
        int p = t >> 3, c4 = t & 7;
        int gi = ti0 + (p >> 3), gj = tj0 + (p & 7);
        ((float4*)sq)[t] = ((const float4*)(g_q + (bbase + (gi << 7) + gj) * 32))[c4];
    }
    __syncthreads();

    int lane = tid & 31, a = tid >> 5;
    int d = min(lane, 24);
    int dr = d / 5, dc = d - dr*5;

    for (int cc = 0; cc < 8; cc++) {
        int p = a*8 + cc;
        int hidx = (a + dr)*12 + (cc + dc);
        const float* skp = sk + hidx;
        const float* sqp = sq + p*32;
        float s = 0.f;
        #pragma unroll
        for (int c = 0; c < 32; c++) s += sqp[c] * skp[c*145];
        if (lane < 25) {
            size_t gp = bbase + ((ti0 + a) << 7) + (tj0 + cc);
            g_w[gp*25 + lane] = __expf(s);
        }
    }
}

// ---------------- propagation: weighted 5x5 stencil + L2-normalize ----------
// 16x4 tile / block (64 px, grid stays 512 = single wave), 256 threads,
// warp = TWO adjacent tile columns x 4 row-outputs, lane = 4 adjacent
// channels (LDG.128). Per halo row the warp loads a 6-pixel window serving
// both columns: LDG per output drops 7.5 -> 6.0 and halo rows 12 -> 8.
// hr-outer; weights (w,w)-duplicated in smem, 2x LDS.128 + 1x LDS.64 per
// (output,row). Direct-global halo reads (L1-served reuse), no barriers.
#define PROP_W_F2 (64*32)     // 64 ops x 32 float2 (row stride 6, padded)
__global__ __launch_bounds__(256, 4) void prop_k(const float* __restrict__ hinit, int it) {
    __shared__ float2 shw[PROP_W_F2];                // 16 KB

    const float* hin = (it == 0) ? hinit : ((it & 1) ? g_hA : g_hB);
    float*       hout = (it & 1) ? g_hB : g_hA;

    int b = blockIdx.z;
    int ti0 = blockIdx.y << 2, tj0 = blockIdx.x << 4;   // 4-high, 16-wide
    int tid = threadIdx.x;
    int lane = tid & 31, c = tid >> 5;               // warp = columns 2c, 2c+1

    const float* hb = hin + ((size_t)b << 21);       // b*N*128
    float* hob = hout + ((size_t)b << 21);

    // stage weights: (w,w) pairs; op = a*16 + col; row r at f2 off op*32 + r*6
    const float* wb = g_w + ((size_t)b << 14) * 25;
    for (int t = tid; t < 1600; t += 256) {
        int op = t / 25, d = t - op*25;
        int a = op >> 4, col = op & 15;
        int r = d / 5, cl = d - r*5;
        float ww = wb[(size_t)(((ti0 + a) << 7) | (tj0 + col)) * 25 + d];
        shw[op*32 + r*6 + cl] = make_float2(ww, ww);
    }
    __syncthreads();

    const unsigned long long* shw64 = (const unsigned long long*)shw;

    // hr-invariant column element-offsets for this warp's 6-pixel window
    unsigned cOff[6];
    #pragma unroll
    for (int dj = 0; dj < 6; dj++) {
        int gj = min(max(tj0 + 2*c + dj - 2, 0), WW-1);
        cOff[dj] = (unsigned)gj << 7;
    }
    const float* hpl = hb + 4*lane;                  // lane's 4-channel base

    // acc[k][a]: column k (0/1), row-output a (0..3); 2 u64 each (4 channels)
    unsigned long long a0[2][4], a1[2][4];
    #pragma unroll
    for (int k = 0; k < 2; k++)
        #pragma unroll
        for (int a = 0; a < 4; a++) { a0[k][a] = 0ull; a1[k][a] = 0ull; }

    #pragma unroll
    for (int hr = 0; hr < 8; hr++) {
        int gi = min(max(ti0 + hr - 2, 0), HH-1);
        const float* rowp = hpl + ((size_t)gi << 14);
        unsigned long long h0[6], h1[6];
        #pragma unroll
        for (int dj = 0; dj < 6; dj++) {
            ulonglong2 hv = *(const ulonglong2*)(rowp + cOff[dj]);   // LDG.128
            h0[dj] = hv.x; h1[dj] = hv.y;
        }
        #pragma unroll
        for (int a = 0; a < 4; a++) {
            if (a > hr || a + 4 < hr) continue;          // compile-time pruned
            #pragma unroll
            for (int k = 0; k < 2; k++) {
                const unsigned long long* wr =
                    shw64 + (a*16 + 2*c + k)*32 + (hr - a)*6;
                ulonglong2 p01 = *(const ulonglong2*)(wr);   // (w0,w0),(w1,w1)
                ulonglong2 p23 = *(const ulonglong2*)(wr + 2);
                unsigned long long p4 = wr[4];
                asm("fma.rn.f32x2 %0, %1, %2, %0;" : "+l"(a0[k][a]) : "l"(h0[k+0]), "l"(p01.x));
                asm("fma.rn.f32x2 %0, %1, %2, %0;" : "+l"(a1[k][a]) : "l"(h1[k+0]), "l"(p01.x));
                asm("fma.rn.f32x2 %0, %1, %2, %0;" : "+l"(a0[k][a]) : "l"(h0[k+1]), "l"(p01.y));
                asm("fma.rn.f32x2 %0, %1, %2, %0;" : "+l"(a1[k][a]) : "l"(h1[k+1]), "l"(p01.y));
                asm("fma.rn.f32x2 %0, %1, %2, %0;" : "+l"(a0[k][a]) : "l"(h0[k+2]), "l"(p23.x));
                asm("fma.rn.f32x2 %0, %1, %2, %0;" : "+l"(a1[k][a]) : "l"(h1[k+2]), "l"(p23.x));
                asm("fma.rn.f32x2 %0, %1, %2, %0;" : "+l"(a0[k][a]) : "l"(h0[k+3]), "l"(p23.y));
                asm("fma.rn.f32x2 %0, %1, %2, %0;" : "+l"(a1[k][a]) : "l"(h1[k+3]), "l"(p23.y));
                asm("fma.rn.f32x2 %0, %1, %2, %0;" : "+l"(a0[k][a]) : "l"(h0[k+4]), "l"(p4));
                asm("fma.rn.f32x2 %0, %1, %2, %0;" : "+l"(a1[k][a]) : "l"(h1[k+4]), "l"(p4));
            }
        }
    }

    #pragma unroll
    for (int k = 0; k < 2; k++)
        #pragma unroll
        for (int a = 0; a < 4; a++) {
            float x0, y0, z0, w0;
            asm("mov.b64 {%0,%1}, %2;" : "=f"(x0), "=f"(y0) : "l"(a0[k][a]));
            asm("mov.b64 {%0,%1}, %2;" : "=f"(z0), "=f"(w0) : "l"(a1[k][a]));
            float ss = x0*x0 + y0*y0 + z0*z0 + w0*w0;
            #pragma unroll
            for (int o = 16; o; o >>= 1) ss += __shfl_xor_sync(0xffffffffu, ss, o);
            float inv = 1.f / (sqrtf(ss) + EPSF);
            float* po = hob + ((size_t)(((ti0 + a) << 7) | (tj0 + 2*c + k)) << 7);
            ((float4*)po)[lane] = make_float4(x0*inv, y0*inv, z0*inv, w0*inv);
        }
}

// ---------------- mask head: h @ w_mask, softmax over M, NCHW out -----------
__global__ void masks_k(const float* __restrict__ wm, float* __restrict__ out) {
    __shared__ float swm[QQ*MM];
    for (int t = threadIdx.x; t < QQ*MM; t += 256) swm[t] = wm[t];
    __syncthreads();

    int gid = blockIdx.x * 256 + threadIdx.x;
    int b = gid >> 14, p = gid & (NN-1);
    const float* hr = g_hB + (size_t)gid * QQ;  // it=31 (odd) wrote hB

    float lg[MM];
    #pragma unroll
    for (int m = 0; m < MM; m++) lg[m] = 0.f;
    for (int q = 0; q < QQ; q++) {
        float hv = hr[q];
        #pragma unroll
        for (int m = 0; m < MM; m++) lg[m] += hv * swm[q*MM + m];
    }
    float mx = lg[0];
    #pragma unroll
    for (int m = 1; m < MM; m++) mx = fmaxf(mx, lg[m]);
    float s = 0.f;
    #pragma unroll
    for (int m = 0; m < MM; m++) { lg[m] = __expf(lg[m] - mx); s += lg[m]; }
    float r = 1.f / s;
    #pragma unroll
    for (int m = 0; m < MM; m++)
        out[(((size_t)(b*MM + m)) << 14) + p] = lg[m] * r;
}

// ---------------- launch ----------------------------------------------------
extern "C" void kernel_launch(void* const* d_in, const int* in_sizes, int n_in,
                              void* d_out, int out_size) {
    const float* x    = (const float*)d_in[0];
    // d_in[1] = edges (int32) — edge structure is analytic, unused
    const float* wc1  = (const float*)d_in[2];
    const float* bc1  = (const float*)d_in[3];
    const float* wc2  = (const float*)d_in[4];
    const float* bc2  = (const float*)d_in[5];
    const float* wk   = (const float*)d_in[6];
    const float* bk   = (const float*)d_in[7];
    const float* wq   = (const float*)d_in[8];
    const float* init = (const float*)d_in[9];
    const float* wm   = (const float*)d_in[10];
    float* out = (float*)d_out;

    conv1_k  <<<BB*NN/64, 512>>>(x, wc1, bc1);
    conv2kq_k<<<BB*NN/64, 512>>>(wc2, bc2, wk, bk, wq);
    edgew_k  <<<dim3(WW/8, HH/8, BB), 256>>>();

    for (int it = 0; it < 32; it++) {
        prop_k<<<dim3(WW/16, HH/4, BB), 256>>>(init, it);
    }
    masks_k<<<BB*NN/256, 256>>>(wm, out);
}

// round 15
// speedup vs baseline: 1.6772x; 1.6772x over previous
#include <cuda_runtime.h>
#include <math.h>

#define HH 128
#define WW 128
#define NN 16384          // H*W
#define BB 2
#define DD 32
#define QQ 128
#define MM 16
#define EPSF 1e-8f

// ---------------- scratch (static device allocations; no cudaMalloc) --------
__device__ float g_feat1[BB*NN*DD];
__device__ float g_k   [BB*NN*DD];   // pre-normalized k-hat
__device__ float g_q   [BB*NN*DD];   // pre-normalized q-hat
__device__ float g_w   [BB*NN*25];   // unnormalized exp(cos) weights
__device__ float g_hA  [BB*NN*QQ];
__device__ float g_hB  [BB*NN*QQ];

// ---------------- conv1: (B,H,W,3) -> relu -> (B,H,W,32) --------------------
__global__ __launch_bounds__(512) void conv1_k(const float* __restrict__ x,
                        const float* __restrict__ w,
                        const float* __restrict__ bias) {
    __shared__ float sw[3*3*3*32];
    __shared__ float sb[32];
    for (int t = threadIdx.x; t < 864; t += 512) sw[t] = w[t];
    if (threadIdx.x < 32) sb[threadIdx.x] = bias[threadIdx.x];
    __syncthreads();

    int warp = threadIdx.x >> 5;
    int co   = threadIdx.x & 31;

    #pragma unroll
    for (int ii = 0; ii < 4; ii++) {
        int gid = blockIdx.x * 64 + ii*16 + warp;    // pixel in [0, B*N)
        int b = gid >> 14, p = gid & (NN-1);
        int i = p >> 7, j = p & 127;

        float acc = sb[co];
        #pragma unroll
        for (int ky = 0; ky < 3; ky++) {
            int yi = i + ky - 1;
            if ((unsigned)yi >= HH) continue;
            #pragma unroll
            for (int kx = 0; kx < 3; kx++) {
                int xj = j + kx - 1;
                if ((unsigned)xj >= WW) continue;
                const float* xp = x + ((size_t)((b << 14) | (yi << 7) | xj)) * 3;
                const float* wp = sw + (ky*3 + kx) * 3 * 32;
                #pragma unroll
                for (int ci = 0; ci < 3; ci++) acc += xp[ci] * wp[ci*32 + co];
            }
        }
        g_feat1[(size_t)gid*32 + co] = fmaxf(acc, 0.f);
    }
}

// ------- conv2 + fused k/q projection + normalization (k-hat, q-hat) --------
__global__ __launch_bounds__(512) void conv2kq_k(const float* __restrict__ w,
                          const float* __restrict__ bias,
                          const float* __restrict__ wk,
                          const float* __restrict__ bk,
                          const float* __restrict__ wq) {
    __shared__ float sw[3*3*32*32];
    __shared__ float swk[1024], swq[1024];
    __shared__ float sb[32], sbk[32];
    for (int t = threadIdx.x; t < 9216; t += 512) sw[t] = w[t];
    for (int t = threadIdx.x; t < 1024; t += 512) { swk[t] = wk[t]; swq[t] = wq[t]; }
    if (threadIdx.x < 32) { sb[threadIdx.x] = bias[threadIdx.x]; sbk[threadIdx.x] = bk[threadIdx.x]; }
    __syncthreads();

    int warp = threadIdx.x >> 5;
    int co   = threadIdx.x & 31;

    #pragma unroll 1
    for (int ii = 0; ii < 4; ii++) {
        int gid = blockIdx.x * 64 + ii*16 + warp;
        int b = gid >> 14, p = gid & (NN-1);
        int i = p >> 7, j = p & 127;

        float acc = sb[co];
        #pragma unroll
        for (int ky = 0; ky < 3; ky++) {
            int yi = i + ky - 1;
            if ((unsigned)yi >= HH) continue;
            #pragma unroll
            for (int kx = 0; kx < 3; kx++) {
                int xj = j + kx - 1;
                if ((unsigned)xj >= WW) continue;
                const float* fin = g_feat1 + ((size_t)((b << 14) | (yi << 7) | xj)) * 32;
                const float* wp  = sw + (ky*3 + kx) * 32 * 32;
                #pragma unroll
                for (int ci = 0; ci < 32; ci++) acc += fin[ci] * wp[ci*32 + co];
            }
        }
        float fv = fmaxf(acc, 0.f);

        float ka = sbk[co], qa = 0.f;
        #pragma unroll
        for (int ci = 0; ci < 32; ci++) {
            float f = __shfl_sync(0xffffffffu, fv, ci);
            ka += f * swk[ci*32 + co];
            qa += f * swq[ci*32 + co];
        }
        float ks = ka*ka, qs = qa*qa;
        #pragma unroll
        for (int o = 16; o; o >>= 1) {
            ks += __shfl_xor_sync(0xffffffffu, ks, o);
            qs += __shfl_xor_sync(0xffffffffu, qs, o);
        }
        float kinv = rsqrtf(fmaxf(ks, 1e-30f));
        float qinv = rsqrtf(fmaxf(qs, 1e-30f));
        g_k[(size_t)gid*32 + co] = ka * kinv;
        g_q[(size_t)gid*32 + co] = qa * qinv;
    }
}

// ---------------- edge weights: exp(dot(q-hat, k-hat)), tile-based ----------
__global__ void edgew_k() {
    __shared__ float sk[32*145];
    __shared__ float sq[64*32];

    int b = blockIdx.z;
    int ti0 = blockIdx.y << 3, tj0 = blockIdx.x << 3;
    int tid = threadIdx.x;
    size_t bbase = (size_t)b << 14;

    for (int t = tid; t < 1152; t += 256) {
        int hp = t >> 3, c4 = t & 7;
        int hr = hp / 12, hc = hp - hr*12;
        int gi = min(max(ti0 + hr - 2, 0), HH-1);
        int gj = min(max(tj0 + hc - 2, 0), WW-1);
        float4 v = ((const float4*)(g_k + (bbase + (gi << 7) + gj) * 32))[c4];
        sk[(c4*4+0)*145 + hp] = v.x;
        sk[(c4*4+1)*145 + hp] = v.y;
        sk[(c4*4+2)*145 + hp] = v.z;
        sk[(c4*4+3)*145 + hp] = v.w;
    }
    for (int t = tid; t < 512; t += 256) {
        int p = t >> 3, c4 = t & 7;
        int gi = ti0 + (p >> 3), gj = tj0 + (p & 7);
        ((float4*)sq)[t] = ((const float4*)(g_q + (bbase + (gi << 7) + gj) * 32))[c4];
    }
    __syncthreads();

    int lane = tid & 31, a = tid >> 5;
    int d = min(lane, 24);
    int dr = d / 5, dc = d - dr*5;

    for (int cc = 0; cc < 8; cc++) {
        int p = a*8 + cc;
        int hidx = (a + dr)*12 + (cc + dc);
        const float* skp = sk + hidx;
        const float* sqp = sq + p*32;
        float s = 0.f;
        #pragma unroll
        for (int c = 0; c < 32; c++) s += sqp[c] * skp[c*145];
        if (lane < 25) {
            size_t gp = bbase + ((ti0 + a) << 7) + (tj0 + cc);
            g_w[gp*25 + lane] = __expf(s);
        }
    }
}

// ---------------- propagation: weighted 5x5 stencil + L2-normalize ----------
// R12's measured-best structure: 8x8 tile / block, 256 threads, warp = tile
// column, lane = 4 adjacent channels (LDG.128), hr-outer, direct-global halo
// reads, (w,w)-pair weights in smem (2x LDS.128 + 1x LDS.64 per output,row).
// CHANGE vs R12: weights for column c are consumed ONLY by warp c, so each
// warp stages its own 200 weights + __syncwarp() -- no block-wide barrier,
// no launch-ramp convoy.
#define PROP_W_F2 (64*32)     // 64 ops x 32 float2 (row stride 6, padded)
__global__ __launch_bounds__(256, 4) void prop_k(const float* __restrict__ hinit, int it) {
    __shared__ float2 shw[PROP_W_F2];                // 16 KB

    const float* hin = (it == 0) ? hinit : ((it & 1) ? g_hA : g_hB);
    float*       hout = (it & 1) ? g_hB : g_hA;

    int b = blockIdx.z;
    int ti0 = blockIdx.y << 3, tj0 = blockIdx.x << 3;
    int tid = threadIdx.x;
    int lane = tid & 31, c = tid >> 5;               // warp = tile column

    const float* hb = hin + ((size_t)b << 21);       // b*N*128
    float* hob = hout + ((size_t)b << 21);

    // per-warp weight staging: warp c stages ops {a*8+c}; no block barrier
    const float* wb = g_w + ((size_t)b << 14) * 25;
    for (int i = lane; i < 200; i += 32) {
        int a = i / 25, d = i - a*25;
        int r = d / 5, cl = d - r*5;
        float ww = wb[(size_t)(((ti0 + a) << 7) | (tj0 + c)) * 25 + d];
        shw[(a*8 + c)*32 + r*6 + cl] = make_float2(ww, ww);
    }
    __syncwarp();

    const unsigned long long* shw64 = (const unsigned long long*)shw;

    // hr-invariant column element-offsets for this warp's 5 taps
    unsigned cOff[5];
    #pragma unroll
    for (int dj = 0; dj < 5; dj++) {
        int gj = min(max(tj0 + c + dj - 2, 0), WW-1);
        cOff[dj] = (unsigned)gj << 7;
    }
    const float* hpl = hb + 4*lane;                  // lane's 4-channel base

    unsigned long long acc0[8], acc1[8];
    #pragma unroll
    for (int a = 0; a < 8; a++) { acc0[a] = 0ull; acc1[a] = 0ull; }

    #pragma unroll
    for (int hr = 0; hr < 12; hr++) {
        int gi = min(max(ti0 + hr - 2, 0), HH-1);
        const float* rowp = hpl + ((size_t)gi << 14);
        unsigned long long h0[5], h1[5];
        #pragma unroll
        for (int dj = 0; dj < 5; dj++) {
            ulonglong2 hv = *(const ulonglong2*)(rowp + cOff[dj]);   // LDG.128
            h0[dj] = hv.x; h1[dj] = hv.y;
        }
        #pragma unroll
        for (int a = 0; a < 8; a++) {
            if (a > hr || a + 4 < hr) continue;          // compile-time pruned
            const unsigned long long* wr = shw64 + (a*8 + c)*32 + (hr - a)*6;
            ulonglong2 p01 = *(const ulonglong2*)(wr);   // (w0,w0),(w1,w1)
            ulonglong2 p23 = *(const ulonglong2*)(wr + 2);
            unsigned long long p4 = wr[4];
            asm("fma.rn.f32x2 %0, %1, %2, %0;" : "+l"(acc0[a]) : "l"(h0[0]), "l"(p01.x));
            asm("fma.rn.f32x2 %0, %1, %2, %0;" : "+l"(acc1[a]) : "l"(h1[0]), "l"(p01.x));
            asm("fma.rn.f32x2 %0, %1, %2, %0;" : "+l"(acc0[a]) : "l"(h0[1]), "l"(p01.y));
            asm("fma.rn.f32x2 %0, %1, %2, %0;" : "+l"(acc1[a]) : "l"(h1[1]), "l"(p01.y));
            asm("fma.rn.f32x2 %0, %1, %2, %0;" : "+l"(acc0[a]) : "l"(h0[2]), "l"(p23.x));
            asm("fma.rn.f32x2 %0, %1, %2, %0;" : "+l"(acc1[a]) : "l"(h1[2]), "l"(p23.x));
            asm("fma.rn.f32x2 %0, %1, %2, %0;" : "+l"(acc0[a]) : "l"(h0[3]), "l"(p23.y));
            asm("fma.rn.f32x2 %0, %1, %2, %0;" : "+l"(acc1[a]) : "l"(h1[3]), "l"(p23.y));
            asm("fma.rn.f32x2 %0, %1, %2, %0;" : "+l"(acc0[a]) : "l"(h0[4]), "l"(p4));
            asm("fma.rn.f32x2 %0, %1, %2, %0;" : "+l"(acc1[a]) : "l"(h1[4]), "l"(p4));
        }
    }

    #pragma unroll
    for (int a = 0; a < 8; a++) {
        float x0, y0, z0, w0;
        asm("mov.b64 {%0,%1}, %2;" : "=f"(x0), "=f"(y0) : "l"(acc0[a]));
        asm("mov.b64 {%0,%1}, %2;" : "=f"(z0), "=f"(w0) : "l"(acc1[a]));
        float ss = x0*x0 + y0*y0 + z0*z0 + w0*w0;
        #pragma unroll
        for (int o = 16; o; o >>= 1) ss += __shfl_xor_sync(0xffffffffu, ss, o);
        float inv = 1.f / (sqrtf(ss) + EPSF);
        float* po = hob + ((size_t)(((ti0 + a) << 7) | (tj0 + c)) << 7);
        ((float4*)po)[lane] = make_float4(x0*inv, y0*inv, z0*inv, w0*inv);
    }
}

// ---------------- mask head: h @ w_mask, softmax over M, NCHW out -----------
// h rows read as 32x LDG.128 per thread (was 128x LDG.32): 4x fewer L1
// wavefronts on an 18MB-traffic kernel.
__global__ void masks_k(const float* __restrict__ wm, float* __restrict__ out) {
    __shared__ float swm[QQ*MM];
    for (int t = threadIdx.x; t < QQ*MM; t += 256) swm[t] = wm[t];
    __syncthreads();

    int gid = blockIdx.x * 256 + threadIdx.x;
    int b = gid >> 14, p = gid & (NN-1);
    const float4* hr4 = (const float4*)(g_hB + (size_t)gid * QQ);  // final in hB

    float lg[MM];
    #pragma unroll
    for (int m = 0; m < MM; m++) lg[m] = 0.f;
    #pragma unroll 4
    for (int q4 = 0; q4 < 32; q4++) {
        float4 v = hr4[q4];
        const float* wrow = swm + q4*4*MM;
        #pragma unroll
        for (int m = 0; m < MM; m++) {
            lg[m] += v.x*wrow[m] + v.y*wrow[MM+m]
                   + v.z*wrow[2*MM+m] + v.w*wrow[3*MM+m];
        }
    }
    float mx = lg[0];
    #pragma unroll
    for (int m = 1; m < MM; m++) mx = fmaxf(mx, lg[m]);
    float s = 0.f;
    #pragma unroll
    for (int m = 0; m < MM; m++) { lg[m] = __expf(lg[m] - mx); s += lg[m]; }
    float r = 1.f / s;
    #pragma unroll
    for (int m = 0; m < MM; m++)
        out[(((size_t)(b*MM + m)) << 14) + p] = lg[m] * r;
}

// ---------------- launch ----------------------------------------------------
extern "C" void kernel_launch(void* const* d_in, const int* in_sizes, int n_in,
                              void* d_out, int out_size) {
    const float* x    = (const float*)d_in[0];
    // d_in[1] = edges (int32) — edge structure is analytic, unused
    const float* wc1  = (const float*)d_in[2];
    const float* bc1  = (const float*)d_in[3];
    const float* wc2  = (const float*)d_in[4];
    const float* bc2  = (const float*)d_in[5];
    const float* wk   = (const float*)d_in[6];
    const float* bk   = (const float*)d_in[7];
    const float* wq   = (const float*)d_in[8];
    const float* init = (const float*)d_in[9];
    const float* wm   = (const float*)d_in[10];
    float* out = (float*)d_out;

    conv1_k  <<<BB*NN/64, 512>>>(x, wc1, bc1);
    conv2kq_k<<<BB*NN/64, 512>>>(wc2, bc2, wk, bk, wq);
    edgew_k  <<<dim3(WW/8, HH/8, BB), 256>>>();

    for (int it = 0; it < 32; it++) {
        prop_k<<<dim3(WW/8, HH/8, BB), 256>>>(init, it);
    }
    masks_k<<<BB*NN/256, 256>>>(wm, out);
}

// round 16
// speedup vs baseline: 1.7567x; 1.0474x over previous
#include <cuda_runtime.h>
#include <math.h>

#define HH 128
#define WW 128
#define NN 16384          // H*W
#define BB 2
#define DD 32
#define QQ 128
#define MM 16
#define EPSF 1e-8f

// ---------------- scratch (static device allocations; no cudaMalloc) --------
__device__ float g_feat1[BB*NN*DD];
__device__ float g_k   [BB*NN*DD];   // pre-normalized k-hat
__device__ float g_q   [BB*NN*DD];   // pre-normalized q-hat
__device__ float g_w   [BB*NN*25];   // unnormalized exp(cos) weights
__device__ float g_hA  [BB*NN*QQ];
__device__ float g_hB  [BB*NN*QQ];

// ---------------- conv1: (B,H,W,3) -> relu -> (B,H,W,32) --------------------
__global__ __launch_bounds__(512) void conv1_k(const float* __restrict__ x,
                        const float* __restrict__ w,
                        const float* __restrict__ bias) {
    __shared__ float sw[3*3*3*32];
    __shared__ float sb[32];
    for (int t = threadIdx.x; t < 864; t += 512) sw[t] = w[t];
    if (threadIdx.x < 32) sb[threadIdx.x] = bias[threadIdx.x];
    __syncthreads();

    int warp = threadIdx.x >> 5;
    int co   = threadIdx.x & 31;

    #pragma unroll
    for (int ii = 0; ii < 4; ii++) {
        int gid = blockIdx.x * 64 + ii*16 + warp;    // pixel in [0, B*N)
        int b = gid >> 14, p = gid & (NN-1);
        int i = p >> 7, j = p & 127;

        float acc = sb[co];
        #pragma unroll
        for (int ky = 0; ky < 3; ky++) {
            int yi = i + ky - 1;
            if ((unsigned)yi >= HH) continue;
            #pragma unroll
            for (int kx = 0; kx < 3; kx++) {
                int xj = j + kx - 1;
                if ((unsigned)xj >= WW) continue;
                const float* xp = x + ((size_t)((b << 14) | (yi << 7) | xj)) * 3;
                const float* wp = sw + (ky*3 + kx) * 3 * 32;
                #pragma unroll
                for (int ci = 0; ci < 3; ci++) acc += xp[ci] * wp[ci*32 + co];
            }
        }
        g_feat1[(size_t)gid*32 + co] = fmaxf(acc, 0.f);
    }
}

// ------- conv2 + fused k/q projection + normalization (k-hat, q-hat) --------
__global__ __launch_bounds__(512) void conv2kq_k(const float* __restrict__ w,
                          const float* __restrict__ bias,
                          const float* __restrict__ wk,
                          const float* __restrict__ bk,
                          const float* __restrict__ wq) {
    __shared__ float sw[3*3*32*32];
    __shared__ float swk[1024], swq[1024];
    __shared__ float sb[32], sbk[32];
    for (int t = threadIdx.x; t < 9216; t += 512) sw[t] = w[t];
    for (int t = threadIdx.x; t < 1024; t += 512) { swk[t] = wk[t]; swq[t] = wq[t]; }
    if (threadIdx.x < 32) { sb[threadIdx.x] = bias[threadIdx.x]; sbk[threadIdx.x] = bk[threadIdx.x]; }
    __syncthreads();

    int warp = threadIdx.x >> 5;
    int co   = threadIdx.x & 31;

    #pragma unroll 1
    for (int ii = 0; ii < 4; ii++) {
        int gid = blockIdx.x * 64 + ii*16 + warp;
        int b = gid >> 14, p = gid & (NN-1);
        int i = p >> 7, j = p & 127;

        float acc = sb[co];
        #pragma unroll
        for (int ky = 0; ky < 3; ky++) {
            int yi = i + ky - 1;
            if ((unsigned)yi >= HH) continue;
            #pragma unroll
            for (int kx = 0; kx < 3; kx++) {
                int xj = j + kx - 1;
                if ((unsigned)xj >= WW) continue;
                const float* fin = g_feat1 + ((size_t)((b << 14) | (yi << 7) | xj)) * 32;
                const float* wp  = sw + (ky*3 + kx) * 32 * 32;
                #pragma unroll
                for (int ci = 0; ci < 32; ci++) acc += fin[ci] * wp[ci*32 + co];
            }
        }
        float fv = fmaxf(acc, 0.f);

        float ka = sbk[co], qa = 0.f;
        #pragma unroll
        for (int ci = 0; ci < 32; ci++) {
            float f = __shfl_sync(0xffffffffu, fv, ci);
            ka += f * swk[ci*32 + co];
            qa += f * swq[ci*32 + co];
        }
        float ks = ka*ka, qs = qa*qa;
        #pragma unroll
        for (int o = 16; o; o >>= 1) {
            ks += __shfl_xor_sync(0xffffffffu, ks, o);
            qs += __shfl_xor_sync(0xffffffffu, qs, o);
        }
        float kinv = rsqrtf(fmaxf(ks, 1e-30f));
        float qinv = rsqrtf(fmaxf(qs, 1e-30f));
        g_k[(size_t)gid*32 + co] = ka * kinv;
        g_q[(size_t)gid*32 + co] = qa * qinv;
    }
}

// ---------------- edge weights: exp(dot(q-hat, k-hat)), tile-based ----------
__global__ void edgew_k() {
    __shared__ float sk[32*145];
    __shared__ float sq[64*32];

    int b = blockIdx.z;
    int ti0 = blockIdx.y << 3, tj0 = blockIdx.x << 3;
    int tid = threadIdx.x;
    size_t bbase = (size_t)b << 14;

    for (int t = tid; t < 1152; t += 256) {
        int hp = t >> 3, c4 = t & 7;
        int hr = hp / 12, hc = hp - hr*12;
        int gi = min(max(ti0 + hr - 2, 0), HH-1);
        int gj = min(max(tj0 + hc - 2, 0), WW-1);
        float4 v = ((const float4*)(g_k + (bbase + (gi << 7) + gj) * 32))[c4];
        sk[(c4*4+0)*145 + hp] = v.x;
        sk[(c4*4+1)*145 + hp] = v.y;
        sk[(c4*4+2)*145 + hp] = v.z;
        sk[(c4*4+3)*145 + hp] = v.w;
    }
    for (int t = tid; t < 512; t += 256) {
        int p = t >> 3, c4 = t & 7;
        int gi = ti0 + (p >> 3), gj = tj0 + (p & 7);
        ((float4*)sq)[t] = ((const float4*)(g_q + (bbase + (gi << 7) + gj) * 32))[c4];
    }
    __syncthreads();

    int lane = tid & 31, a = tid >> 5;
    int d = min(lane, 24);
    int dr = d / 5, dc = d - dr*5;

    for (int cc = 0; cc < 8; cc++) {
        int p = a*8 + cc;
        int hidx = (a + dr)*12 + (cc + dc);
        const float* skp = sk + hidx;
        const float* sqp = sq + p*32;
        float s = 0.f;
        #pragma unroll
        for (int c = 0; c < 32; c++) s += sqp[c] * skp[c*145];
        if (lane < 25) {
            size_t gp = bbase + ((ti0 + a) << 7) + (tj0 + cc);
            g_w[gp*25 + lane] = __expf(s);
        }
    }
}

// ---------------- propagation: weighted 5x5 stencil + L2-normalize ----------
// Same per-warp code as the measured-best R15 kernel (warp = tile column,
// lane = 4 adjacent channels, hr-outer, direct-global LDG.128 halo reads,
// per-warp (w,w)-pair weight staging, no block barriers) -- but repackaged
// into 128-thread CTAs over a 4x8 tile: grid 512 -> 1024 blocks, 6.92/SM,
// cutting the wave-quantization idle from 15.6% to 1.2%. Residency: 8 blocks
// x 128 thr x 64 regs = full RF, 8KB smem/block.
#define PROP_W_F2 (32*32)     // 32 ops x 32 float2 (row stride 6, padded)
__global__ __launch_bounds__(128, 8) void prop_k(const float* __restrict__ hinit, int it) {
    __shared__ float2 shw[PROP_W_F2];                // 8 KB

    const float* hin = (it == 0) ? hinit : ((it & 1) ? g_hA : g_hB);
    float*       hout = (it & 1) ? g_hB : g_hA;

    int b = blockIdx.z;
    int ti0 = blockIdx.y << 3, tj0 = blockIdx.x << 2;   // 8-high, 4-wide
    int tid = threadIdx.x;
    int lane = tid & 31, c = tid >> 5;               // warp = tile column (0-3)

    const float* hb = hin + ((size_t)b << 21);       // b*N*128
    float* hob = hout + ((size_t)b << 21);

    // per-warp weight staging: warp c stages ops {a*4+c}; no block barrier
    const float* wb = g_w + ((size_t)b << 14) * 25;
    for (int i = lane; i < 200; i += 32) {
        int a = i / 25, d = i - a*25;
        int r = d / 5, cl = d - r*5;
        float ww = wb[(size_t)(((ti0 + a) << 7) | (tj0 + c)) * 25 + d];
        shw[(a*4 + c)*32 + r*6 + cl] = make_float2(ww, ww);
    }
    __syncwarp();

    const unsigned long long* shw64 = (const unsigned long long*)shw;

    // hr-invariant column element-offsets for this warp's 5 taps
    unsigned cOff[5];
    #pragma unroll
    for (int dj = 0; dj < 5; dj++) {
        int gj = min(max(tj0 + c + dj - 2, 0), WW-1);
        cOff[dj] = (unsigned)gj << 7;
    }
    const float* hpl = hb + 4*lane;                  // lane's 4-channel base

    unsigned long long acc0[8], acc1[8];
    #pragma unroll
    for (int a = 0; a < 8; a++) { acc0[a] = 0ull; acc1[a] = 0ull; }

    #pragma unroll
    for (int hr = 0; hr < 12; hr++) {
        int gi = min(max(ti0 + hr - 2, 0), HH-1);
        const float* rowp = hpl + ((size_t)gi << 14);
        unsigned long long h0[5], h1[5];
        #pragma unroll
        for (int dj = 0; dj < 5; dj++) {
            ulonglong2 hv = *(const ulonglong2*)(rowp + cOff[dj]);   // LDG.128
            h0[dj] = hv.x; h1[dj] = hv.y;
        }
        #pragma unroll
        for (int a = 0; a < 8; a++) {
            if (a > hr || a + 4 < hr) continue;          // compile-time pruned
            const unsigned long long* wr = shw64 + (a*4 + c)*32 + (hr - a)*6;
            ulonglong2 p01 = *(const ulonglong2*)(wr);   // (w0,w0),(w1,w1)
            ulonglong2 p23 = *(const ulonglong2*)(wr + 2);
            unsigned long long p4 = wr[4];
            asm("fma.rn.f32x2 %0, %1, %2, %0;" : "+l"(acc0[a]) : "l"(h0[0]), "l"(p01.x));
            asm("fma.rn.f32x2 %0, %1, %2, %0;" : "+l"(acc1[a]) : "l"(h1[0]), "l"(p01.x));
            asm("fma.rn.f32x2 %0, %1, %2, %0;" : "+l"(acc0[a]) : "l"(h0[1]), "l"(p01.y));
            asm("fma.rn.f32x2 %0, %1, %2, %0;" : "+l"(acc1[a]) : "l"(h1[1]), "l"(p01.y));
            asm("fma.rn.f32x2 %0, %1, %2, %0;" : "+l"(acc0[a]) : "l"(h0[2]), "l"(p23.x));
            asm("fma.rn.f32x2 %0, %1, %2, %0;" : "+l"(acc1[a]) : "l"(h1[2]), "l"(p23.x));
            asm("fma.rn.f32x2 %0, %1, %2, %0;" : "+l"(acc0[a]) : "l"(h0[3]), "l"(p23.y));
            asm("fma.rn.f32x2 %0, %1, %2, %0;" : "+l"(acc1[a]) : "l"(h1[3]), "l"(p23.y));
            asm("fma.rn.f32x2 %0, %1, %2, %0;" : "+l"(acc0[a]) : "l"(h0[4]), "l"(p4));
            asm("fma.rn.f32x2 %0, %1, %2, %0;" : "+l"(acc1[a]) : "l"(h1[4]), "l"(p4));
        }
    }

    #pragma unroll
    for (int a = 0; a < 8; a++) {
        float x0, y0, z0, w0;
        asm("mov.b64 {%0,%1}, %2;" : "=f"(x0), "=f"(y0) : "l"(acc0[a]));
        asm("mov.b64 {%0,%1}, %2;" : "=f"(z0), "=f"(w0) : "l"(acc1[a]));
        float ss = x0*x0 + y0*y0 + z0*z0 + w0*w0;
        #pragma unroll
        for (int o = 16; o; o >>= 1) ss += __shfl_xor_sync(0xffffffffu, ss, o);
        float inv = 1.f / (sqrtf(ss) + EPSF);
        float* po = hob + ((size_t)(((ti0 + a) << 7) | (tj0 + c)) << 7);
        ((float4*)po)[lane] = make_float4(x0*inv, y0*inv, z0*inv, w0*inv);
    }
}

// ---------------- mask head: h @ w_mask, softmax over M, NCHW out -----------
__global__ void masks_k(const float* __restrict__ wm, float* __restrict__ out) {
    __shared__ float swm[QQ*MM];
    for (int t = threadIdx.x; t < QQ*MM; t += 256) swm[t] = wm[t];
    __syncthreads();

    int gid = blockIdx.x * 256 + threadIdx.x;
    int b = gid >> 14, p = gid & (NN-1);
    const float4* hr4 = (const float4*)(g_hB + (size_t)gid * QQ);  // final in hB

    float lg[MM];
    #pragma unroll
    for (int m = 0; m < MM; m++) lg[m] = 0.f;
    #pragma unroll 4
    for (int q4 = 0; q4 < 32; q4++) {
        float4 v = hr4[q4];
        const float* wrow = swm + q4*4*MM;
        #pragma unroll
        for (int m = 0; m < MM; m++) {
            lg[m] += v.x*wrow[m] + v.y*wrow[MM+m]
                   + v.z*wrow[2*MM+m] + v.w*wrow[3*MM+m];
        }
    }
    float mx = lg[0];
    #pragma unroll
    for (int m = 1; m < MM; m++) mx = fmaxf(mx, lg[m]);
    float s = 0.f;
    #pragma unroll
    for (int m = 0; m < MM; m++) { lg[m] = __expf(lg[m] - mx); s += lg[m]; }
    float r = 1.f / s;
    #pragma unroll
    for (int m = 0; m < MM; m++)
        out[(((size_t)(b*MM + m)) << 14) + p] = lg[m] * r;
}

// ---------------- launch ----------------------------------------------------
extern "C" void kernel_launch(void* const* d_in, const int* in_sizes, int n_in,
                              void* d_out, int out_size) {
    const float* x    = (const float*)d_in[0];
    // d_in[1] = edges (int32) — edge structure is analytic, unused
    const float* wc1  = (const float*)d_in[2];
    const float* bc1  = (const float*)d_in[3];
    const float* wc2  = (const float*)d_in[4];
    const float* bc2  = (const float*)d_in[5];
    const float* wk   = (const float*)d_in[6];
    const float* bk   = (const float*)d_in[7];
    const float* wq   = (const float*)d_in[8];
    const float* init = (const float*)d_in[9];
    const float* wm   = (const float*)d_in[10];
    float* out = (float*)d_out;

    conv1_k  <<<BB*NN/64, 512>>>(x, wc1, bc1);
    conv2kq_k<<<BB*NN/64, 512>>>(wc2, bc2, wk, bk, wq);
    edgew_k  <<<dim3(WW/8, HH/8, BB), 256>>>();

    for (int it = 0; it < 32; it++) {
        prop_k<<<dim3(WW/4, HH/8, BB), 128>>>(init, it);
    }
    masks_k<<<BB*NN/256, 256>>>(wm, out);
}